// round 3
// baseline (speedup 1.0000x reference)
#include <cuda_runtime.h>
#include <cuda_bf16.h>
#include <math.h>

// Problem constants (from reference): N_CUTS=4e6, DIM=64, N_CLUSTERS=50, N_VARIANTS=2000
#define DIM 64
#define MAX_SEG 100000

// Scratch for raw segment sums: 100000 * 64 floats = 25.6 MB (static: allocation-free rule)
__device__ float g_raw[(size_t)MAX_SEG * DIM];

__device__ __forceinline__ float4 f4add(float4 a, float4 b) {
    return make_float4(a.x + b.x, a.y + b.y, a.z + b.z, a.w + b.w);
}

// ---------------------------------------------------------------------------
// Kernel 1: CSR segment sum, warp-per-segment.
//   lane = h*16 + q : h = row half (0/1), q = float4 index within row (0..15)
//   Each warp iterates its segment's contiguous rows 8 at a time
//   (4 unrolled steps x 2 rows), 4 independent float4 accumulators -> MLP=4.
//   Cross-row-half combine via shfl.down 16; lanes 0..15 store the 64-float
//   result as one coalesced 256B float4 store.
// indptr dtype (int32 vs int64) is detected inline: if int64 (values << 2^31),
// all odd 32-bit words are zero; 32 sorted random breakpoints can't all be 0.
// ---------------------------------------------------------------------------
__global__ void __launch_bounds__(256) seg_sum_kernel(
    const float4* __restrict__ emb,   // [n_cuts * 16] float4 (row = 16 float4)
    const int* __restrict__ ipw,      // indptr as 32-bit words
    float* __restrict__ raw,          // [n_seg * 64]
    int n_seg)
{
    const int lane = threadIdx.x & 31;
    const int wid  = threadIdx.x >> 5;
    const int s    = blockIdx.x * 8 + wid;
    if (s >= n_seg) return;

    // inline dtype detection (first 256B of indptr, L1/L2-hot)
    const unsigned odd_nonzero =
        __ballot_sync(0xffffffffu, ipw[2 * lane + 1] != 0);
    long long r0, r1;
    if (odd_nonzero == 0u) {  // int64
        const long long* ip = (const long long*)ipw;
        r0 = __ldg(&ip[s]); r1 = __ldg(&ip[s + 1]);
    } else {                   // int32
        r0 = (long long)__ldg(&ipw[s]); r1 = (long long)__ldg(&ipw[s + 1]);
    }

    const int q = lane & 15;
    const int h = lane >> 4;

    float4 a0 = make_float4(0.f, 0.f, 0.f, 0.f);
    float4 a1 = a0, a2 = a0, a3 = a0;
    const float4 zero = a0;

    // rows r0+h, r0+h+2, ... ; 8 rows per warp iteration
    for (long long r = r0 + h; r < r1; r += 8) {
        const float4* p = emb + r * 16 + q;
        float4 v0 = __ldg(p);
        float4 v1 = (r + 2 < r1) ? __ldg(p + 32) : zero;
        float4 v2 = (r + 4 < r1) ? __ldg(p + 64) : zero;
        float4 v3 = (r + 6 < r1) ? __ldg(p + 96) : zero;
        a0 = f4add(a0, v0);
        a1 = f4add(a1, v1);
        a2 = f4add(a2, v2);
        a3 = f4add(a3, v3);
    }

    float4 acc = f4add(f4add(a0, a1), f4add(a2, a3));
    acc.x += __shfl_down_sync(0xffffffffu, acc.x, 16);
    acc.y += __shfl_down_sync(0xffffffffu, acc.y, 16);
    acc.z += __shfl_down_sync(0xffffffffu, acc.z, 16);
    acc.w += __shfl_down_sync(0xffffffffu, acc.w, 16);

    if (h == 0) {
        ((float4*)(raw + (long long)s * DIM))[q] = acc;
    }
}

// ---------------------------------------------------------------------------
// Kernel 2: per-(variant, dim4) normalization across clusters (vectorized).
//   ve = log1p(raw / lib[c]) - 2 ; mean/std (ddof=1) over clusters;
//   rel = (ve - mean)/(std + 1e-5).
// Statistics on UNSHIFTED y = log1p(raw/lib): the -2 offset would cause
// catastrophic fp32 cancellation (std ~ 6e-5 vs values ~ 2). Two passes over
// c; second pass hits L2 (25.6 MB << 126 MB L2).
// ---------------------------------------------------------------------------
__global__ void finalize_kernel(
    const float4* __restrict__ raw,  // [n_clusters * n_variants * 16] float4
    const float* __restrict__ lib,   // [n_clusters]
    float4* __restrict__ out,        // [n_clusters * n_variants * 32] float4
    int n_clusters, int n_variants)
{
    const int idx = blockIdx.x * blockDim.x + threadIdx.x; // v*16 + q
    const int total = n_variants * 16;
    if (idx >= total) return;

    const int v = idx >> 4;
    const int q = idx & 15;

    const long long base = (long long)v * 16 + q;
    const long long cstride = (long long)n_variants * 16;

    float4 sum = make_float4(0.f, 0.f, 0.f, 0.f);
    float4 ssq = sum;
    for (int c = 0; c < n_clusters; ++c) {
        float inv = 1.f / __ldg(&lib[c]);
        float4 r = __ldg(&raw[base + (long long)c * cstride]);
        float4 y = make_float4(log1pf(r.x * inv), log1pf(r.y * inv),
                               log1pf(r.z * inv), log1pf(r.w * inv));
        sum = f4add(sum, y);
        ssq.x += y.x * y.x; ssq.y += y.y * y.y;
        ssq.z += y.z * y.z; ssq.w += y.w * y.w;
    }

    const float invn = 1.f / (float)n_clusters;
    const float invn1 = 1.f / (float)(n_clusters - 1);
    float4 mean = make_float4(sum.x * invn, sum.y * invn, sum.z * invn, sum.w * invn);
    float4 idn;
    idn.x = 1.f / (sqrtf(fmaxf((ssq.x - sum.x * mean.x) * invn1, 0.f)) + 1e-5f);
    idn.y = 1.f / (sqrtf(fmaxf((ssq.y - sum.y * mean.y) * invn1, 0.f)) + 1e-5f);
    idn.z = 1.f / (sqrtf(fmaxf((ssq.z - sum.z * mean.z) * invn1, 0.f)) + 1e-5f);
    idn.w = 1.f / (sqrtf(fmaxf((ssq.w - sum.w * mean.w) * invn1, 0.f)) + 1e-5f);

    for (int c = 0; c < n_clusters; ++c) {
        float inv = 1.f / __ldg(&lib[c]);
        float4 r = __ldg(&raw[base + (long long)c * cstride]);
        float4 y = make_float4(log1pf(r.x * inv), log1pf(r.y * inv),
                               log1pf(r.z * inv), log1pf(r.w * inv));
        long long o = ((long long)c * n_variants + v) * 32; // 128 floats = 32 float4
        out[o + q] = make_float4(y.x - 2.f, y.y - 2.f, y.z - 2.f, y.w - 2.f);
        out[o + 16 + q] = make_float4((y.x - mean.x) * idn.x, (y.y - mean.y) * idn.y,
                                      (y.z - mean.z) * idn.z, (y.w - mean.w) * idn.w);
    }
}

extern "C" void kernel_launch(void* const* d_in, const int* in_sizes, int n_in,
                              void* d_out, int out_size)
{
    const float* emb    = (const float*)d_in[0];   // [n_cuts, 64] fp32
    const float* lib    = (const float*)d_in[1];   // [n_clusters] fp32
    const int*   indptr = (const int*)d_in[2];     // [n_seg + 1] int32 OR int64 words

    const int n_clusters = in_sizes[1];
    const int n_seg      = in_sizes[2] - 1;
    const int n_variants = n_seg / n_clusters;

    float* raw;
    cudaGetSymbolAddress((void**)&raw, g_raw);

    // Kernel 1: one warp per segment, 8 warps per block
    const int blocks1 = (n_seg + 7) / 8;
    seg_sum_kernel<<<blocks1, 256>>>((const float4*)emb, indptr, raw, n_seg);

    // Kernel 2: one thread per (variant, float4-of-dims)
    const int total = n_variants * 16;
    const int threads = 256;
    const int blocks2 = (total + threads - 1) / threads;
    finalize_kernel<<<blocks2, threads>>>((const float4*)raw, lib,
                                          (float4*)d_out, n_clusters, n_variants);
}